// round 11
// baseline (speedup 1.0000x reference)
#include <cuda_runtime.h>
#include <cstdint>

#define BB 32
#define CC 512
#define HWP 784
#define MM 200
#define NCC 50
#define NMM 4
#define KK 5

#define MT 32
#define PT 16            // pixels per block tile (8 pairs)
#define CT 8             // channels per pipeline stage
#define NSTEP (CC / CT)  // 64

// smem layout (float2 units), per-channel layout identical to validated R5/R10:
// per channel per operand: 4 groups of 8 rows, group stride 72 f2
// (8 rows x 8 f2 + 8 f2 pad); within each row the four 16B chunks are
// XOR-swizzled by (row&3). Two pipeline buffers (double buffer).
// sden overlays the TAIL of the buffer region (buffers are dead by then);
// fls overlays the head. Total arena = 9216 f2 = 73728 B -> 3 CTAs/SM.
#define CHF2 288                   // 4 * 72
#define STAGEF2 (CT * CHF2)        // 2304 per operand
#define BUFF2 (2 * STAGEF2)        // x + m = 4608
#define SDENF2 8192                // sden overlay offset (fls uses [0,8192))
#define ARENAF2 (2 * BUFF2)        // 9216 f2 = 73728 B

typedef unsigned long long ull;

__device__ float g_bg[BB * KK * HWP];
__device__ float g_pm[BB * MM * KK];

__device__ __forceinline__ unsigned su32(const void* p) {
    return (unsigned)__cvta_generic_to_shared(p);
}

// ---------------------------------------------------------------------------
// bg (+ fused clutter normalization + g_pm zeroing)
// ---------------------------------------------------------------------------
__global__ void __launch_bounds__(256) bg_kernel(const float* __restrict__ x,
                                                 const float* __restrict__ clutter) {
    __shared__ float cls[KK * CC];
    __shared__ float part[16][16 * KK];
    __shared__ float red[8];
    __shared__ float rtot;

    const int tid = threadIdx.x;
    const int b = blockIdx.y;
    const int px0 = blockIdx.x * 16;
    const int lane = tid & 31, w = tid >> 5;

    const int zi = (blockIdx.y * 49 + blockIdx.x) * 256 + tid;
    if (zi < BB * MM * KK) g_pm[zi] = 0.0f;

    for (int k = 0; k < KK; ++k) {
        float v0 = fminf(fmaxf(clutter[k * CC + tid], 0.f), 1.f);
        float v1 = fminf(fmaxf(clutter[k * CC + 256 + tid], 0.f), 1.f);
        float s = v0 + v1;
        #pragma unroll
        for (int o = 16; o > 0; o >>= 1) s += __shfl_xor_sync(0xffffffffu, s, o);
        if (lane == 0) red[w] = s;
        __syncthreads();
        if (tid == 0) {
            float r = 0.f;
            #pragma unroll
            for (int q = 0; q < 8; ++q) r += red[q];
            rtot = fmaxf(r, 1e-12f);
        }
        __syncthreads();
        const float inv = __frcp_rn(rtot);
        cls[k * CC + tid] = v0 * inv;
        cls[k * CC + 256 + tid] = v1 * inv;
        __syncthreads();
    }

    const int px = tid & 15;
    const int cg = tid >> 4;
    float a0 = 0.f, a1 = 0.f, a2 = 0.f, a3 = 0.f, a4 = 0.f;
    const float* xb = x + ((size_t)b * CC + cg * 32) * HWP + px0 + px;
    #pragma unroll 4
    for (int ci = 0; ci < 32; ++ci) {
        const int c = cg * 32 + ci;
        const float xv = xb[(size_t)ci * HWP];
        a0 += xv * cls[0 * CC + c];
        a1 += xv * cls[1 * CC + c];
        a2 += xv * cls[2 * CC + c];
        a3 += xv * cls[3 * CC + c];
        a4 += xv * cls[4 * CC + c];
    }
    part[cg][px * KK + 0] = a0;
    part[cg][px * KK + 1] = a1;
    part[cg][px * KK + 2] = a2;
    part[cg][px * KK + 3] = a3;
    part[cg][px * KK + 4] = a4;
    __syncthreads();

    if (tid < 16 * KK) {
        float s = 0.f;
        #pragma unroll
        for (int g = 0; g < 16; ++g) s += part[g][tid];
        const int p = tid / KK, k = tid % KK;
        g_bg[((size_t)b * KK + k) * HWP + px0 + p] = __logf(s * 0.3f + 1e-10f);
    }
}

// ---------------------------------------------------------------------------
// fg: block 128 = 4bg(warps) x 4mg x 8pc ; thread tile 8b x 8m x 2px (1 pair).
// EXACT validated R10 body; only change: 3 CTAs/SM (single wave for 343
// blocks on 444 slots) with the arena trimmed to 73728B via sden overlay.
// ---------------------------------------------------------------------------
__global__ void __launch_bounds__(128, 3) fg_kernel(const float* __restrict__ x,
                                                    const float* __restrict__ mix) {
    extern __shared__ float2 arena[];
    float2* sden = arena + SDENF2;       // overlay: [m(32)][pc(8)] f2 (post-loop)
    float2* fls  = arena;                // epilogue overlay [b][m][pc]

    const int tid   = threadIdx.x;
    const int mtile = blockIdx.x;        // 7
    const int ptile = blockIdx.y;        // 49
    const int mbase = mtile * MT;
    const int px0   = ptile * PT;

    // ---- loader mapping: c_l = tid>>5 (channels c_l and c_l+4), r = tid&31
    const int c_l = tid >> 5;
    const int r   = tid & 31;
    const int mrow = (mbase + r < MM) ? mbase + r : MM - 1;
    const float* xsrc = x   + ((size_t)r    * CC + c_l) * HWP + px0;
    const float* msrc = mix + ((size_t)mrow * CC + c_l) * HWP + px0;
    const int rowb_f2 = c_l * CHF2 + 72 * (r >> 3) + 8 * (r & 7);
    const int rsw = r & 3;
    const unsigned sm_b = su32(arena);

    // ---- compute mapping (identical to R5/R10)
    const int pc = tid & 7;
    const int mg = (tid >> 3) & 3;
    const int bg = tid >> 5;             // warp id
    int pcx[4];
    #pragma unroll
    for (int t = 0; t < 4; ++t) pcx[t] = 2 * ((pc >> 1) ^ t) + (pc & 1);
    const int xob = bg * 72;
    const int mob = mg * 72;
    const int dof = mob + 8 * bg + pcx[bg];   // dden rows j=bg and j=bg+4

    ull acc[8][8];
    ull dden[2] = {0ull, 0ull};
    #pragma unroll
    for (int i = 0; i < 8; ++i)
        #pragma unroll
        for (int j = 0; j < 8; ++j) acc[i][j] = 0ull;

#define LOAD_STAGE(buf, s)                                                        \
    {                                                                             \
        const size_t go = (size_t)(s) * CT * HWP;                                 \
        _Pragma("unroll")                                                         \
        for (int ch = 0; ch < 2; ++ch) {                                          \
            _Pragma("unroll")                                                     \
            for (int q = 0; q < 4; ++q) {                                         \
                const int df2 = rowb_f2 + ch * (4 * CHF2) + 2 * (q ^ rsw);        \
                unsigned dx = sm_b + (unsigned)(((buf) * BUFF2 + df2) * 8);       \
                unsigned dm = dx + (unsigned)(STAGEF2 * 8);                       \
                asm volatile("cp.async.cg.shared.global [%0], [%1], 16;"          \
                             ::"r"(dx), "l"(xsrc + go + ch * 4 * HWP + 4 * q));   \
                asm volatile("cp.async.cg.shared.global [%0], [%1], 16;"          \
                             ::"r"(dm), "l"(msrc + go + ch * 4 * HWP + 4 * q));   \
            }                                                                     \
        }                                                                         \
        asm volatile("cp.async.commit_group;");                                   \
    }

#define STEP(cur, nxt, s)                                                         \
    {                                                                             \
        asm volatile("cp.async.wait_group 0;");                                   \
        __syncthreads();                                                          \
        {                                                                         \
            const int ns = ((s) + 1 < NSTEP) ? (s) + 1 : NSTEP - 1;               \
            LOAD_STAGE(nxt, ns);                                                  \
        }                                                                         \
        {                                                                         \
            const ull* xb = (const ull*)(arena + (cur) * BUFF2);                  \
            const ull* mb = xb + STAGEF2;                                         \
            _Pragma("unroll")                                                     \
            for (int c = 0; c < CT; ++c) {                                        \
                ull xr[8];                                                        \
                _Pragma("unroll")                                                 \
                for (int i = 0; i < 8; ++i)                                       \
                    xr[i] = xb[c * CHF2 + xob + 8 * i + pcx[i & 3]];              \
                const ull d0 = mb[c * CHF2 + dof];                                \
                const ull d1 = mb[c * CHF2 + dof + 32];                           \
                asm("add.rn.f32x2 %0, %0, %1;" : "+l"(dden[0]) : "l"(d0));        \
                asm("add.rn.f32x2 %0, %0, %1;" : "+l"(dden[1]) : "l"(d1));        \
                _Pragma("unroll")                                                 \
                for (int j = 0; j < 8; ++j) {                                     \
                    const ull mr = mb[c * CHF2 + mob + 8 * j + pcx[j & 3]];       \
                    _Pragma("unroll")                                             \
                    for (int i = 0; i < 8; ++i)                                   \
                        asm("fma.rn.f32x2 %0, %1, %2, %0;"                        \
                            : "+l"(acc[i][j]) : "l"(xr[i]), "l"(mr));             \
                }                                                                 \
            }                                                                     \
        }                                                                         \
    }

    // ---- prologue: stage 0 -> buffer 0
    LOAD_STAGE(0, 0)

    // ---- main loop: 64 steps, unrolled x2 for static buffer indices
    for (int it = 0; it < 32; ++it) {
        const int s = it * 2;
        STEP(0, 1, s)
        STEP(1, 0, s + 1)
    }

    asm volatile("cp.async.wait_group 0;");
    __syncthreads();

    // ---- denominators -> sden (each warp owns m-rows j=bg, bg+4 per mg)
    *(ull*)&sden[(mg * 8 + bg) * 8 + pc] = dden[0];
    *(ull*)&sden[(mg * 8 + bg + 4) * 8 + pc] = dden[1];
    __syncthreads();

    // ---- fl = log(acc/den * 0.7 + 1e-10) -> fls overlay
    #pragma unroll
    for (int j = 0; j < 8; ++j) {
        const float2 d = sden[(mg * 8 + j) * 8 + pc];
        const float ivx = __fdividef(0.7f, fmaxf(d.x, 1e-12f));
        const float ivy = __fdividef(0.7f, fmaxf(d.y, 1e-12f));
        #pragma unroll
        for (int i = 0; i < 8; ++i) {
            const float2 a = *(const float2*)&acc[i][j];
            float2 f;
            f.x = __logf(a.x * ivx + 1e-10f);
            f.y = __logf(a.y * ivy + 1e-10f);
            fls[((bg * 8 + i) * 32 + (mg * 8 + j)) * 8 + pc] = f;
        }
    }
    __syncthreads();

    // ---- occlusion-max + pixel reduction + global accumulate
    #pragma unroll
    for (int rep = 0; rep < 8; ++rep) {
        const int cell = tid + rep * 128;      // 0..1023
        const int b = cell >> 5;
        const int ml = cell & 31;
        const int m_g = mbase + ml;
        float2 fv[8];
        #pragma unroll
        for (int p = 0; p < 8; ++p) fv[p] = fls[cell * 8 + p];
        float sk[KK];
        #pragma unroll
        for (int k = 0; k < KK; ++k) {
            float s = 0.f;
            const float* bgp = g_bg + ((size_t)b * KK + k) * HWP + px0;
            #pragma unroll
            for (int pp = 0; pp < 4; ++pp) {
                const float4 bv = *(const float4*)(bgp + pp * 4);
                s += fmaxf(fv[2 * pp].x, bv.x) + fmaxf(fv[2 * pp].y, bv.y) +
                     fmaxf(fv[2 * pp + 1].x, bv.z) + fmaxf(fv[2 * pp + 1].y, bv.w);
            }
            sk[k] = s;
        }
        if (m_g < MM) {
            float* pmp = g_pm + ((size_t)b * MM + m_g) * KK;
            #pragma unroll
            for (int k = 0; k < KK; ++k) atomicAdd(&pmp[k], sk[k]);
        }
    }
#undef STEP
#undef LOAD_STAGE
}

// ---------------------------------------------------------------------------
__global__ void final_kernel(float* __restrict__ out) {
    const int idx = blockIdx.x * 256 + threadIdx.x;
    if (idx >= BB * NCC) return;
    const int b = idx / NCC, nc = idx % NCC;
    const float* p = g_pm + ((size_t)b * MM + nc * NMM) * KK;
    float m = -3.402823466e+38f;
    #pragma unroll
    for (int t = 0; t < NMM * KK; ++t) m = fmaxf(m, p[t]);
    out[idx] = m;
}

// ---------------------------------------------------------------------------
extern "C" void kernel_launch(void* const* d_in, const int* in_sizes, int n_in,
                              void* d_out, int out_size) {
    const float* x       = (const float*)d_in[0];
    const float* mix     = (const float*)d_in[1];
    const float* clutter = (const float*)d_in[2];
    float* out = (float*)d_out;

    const int fg_smem = ARENAF2 * 8;     // 73728 B -> 3 CTAs/SM
    cudaFuncSetAttribute(fg_kernel, cudaFuncAttributeMaxDynamicSharedMemorySize,
                         fg_smem);

    bg_kernel<<<dim3(49, BB), 256>>>(x, clutter);
    fg_kernel<<<dim3((MM + MT - 1) / MT, HWP / PT), 128, fg_smem>>>(x, mix);
    final_kernel<<<(BB * NCC + 255) / 256, 256>>>(out);
}

// round 13
// speedup vs baseline: 1.2495x; 1.2495x over previous
#include <cuda_runtime.h>
#include <cstdint>

#define BB 32
#define CC 512
#define HWP 784
#define MM 200
#define NCC 50
#define NMM 4
#define KK 5

#define MT 32
#define PT 16            // pixels per block tile (8 pairs)
#define CT 8             // channels per pipeline stage
#define NSPLIT 2
#define CSPLIT (CC / NSPLIT)       // 256 channels per split
#define NSTEP (CSPLIT / CT)        // 32 steps per split
#define NTILE (7 * 49)             // 343 (m,p) tiles

// smem layout (float2 units), per-channel layout identical to validated R10:
// per channel per operand: 4 groups of 8 rows, group stride 72 f2
// (8 rows x 8 f2 + 8 f2 pad); within each row the four 16B chunks are
// XOR-swizzled by (row&3). Two pipeline buffers (double buffer).
#define CHF2 288                   // 4 * 72
#define STAGEF2 (CT * CHF2)        // 2304 per operand
#define BUFF2 (2 * STAGEF2)        // x + m = 4608
#define ARENAF2 (2 * BUFF2)        // 9216 f2 = 73728 B

typedef unsigned long long ull;

__device__ float g_bg[BB * KK * HWP];
__device__ float g_pm[BB * MM * KK];
// C-split partials: [split][tile][b(32)][m(32)][pc(8)] float2  (45 MB)
__device__ float2 g_part[NSPLIT * NTILE * 8192];
// C-split denominators: [split][tile][m(32)][pc(8)] float2  (1.4 MB)
__device__ float2 g_pden[NSPLIT * NTILE * 256];

__device__ __forceinline__ unsigned su32(const void* p) {
    return (unsigned)__cvta_generic_to_shared(p);
}

// ---------------------------------------------------------------------------
// bg (+ fused clutter normalization + g_pm zeroing)
// ---------------------------------------------------------------------------
__global__ void __launch_bounds__(256) bg_kernel(const float* __restrict__ x,
                                                 const float* __restrict__ clutter) {
    __shared__ float cls[KK * CC];
    __shared__ float part[16][16 * KK];
    __shared__ float red[8];
    __shared__ float rtot;

    const int tid = threadIdx.x;
    const int b = blockIdx.y;
    const int px0 = blockIdx.x * 16;
    const int lane = tid & 31, w = tid >> 5;

    const int zi = (blockIdx.y * 49 + blockIdx.x) * 256 + tid;
    if (zi < BB * MM * KK) g_pm[zi] = 0.0f;

    for (int k = 0; k < KK; ++k) {
        float v0 = fminf(fmaxf(clutter[k * CC + tid], 0.f), 1.f);
        float v1 = fminf(fmaxf(clutter[k * CC + 256 + tid], 0.f), 1.f);
        float s = v0 + v1;
        #pragma unroll
        for (int o = 16; o > 0; o >>= 1) s += __shfl_xor_sync(0xffffffffu, s, o);
        if (lane == 0) red[w] = s;
        __syncthreads();
        if (tid == 0) {
            float r = 0.f;
            #pragma unroll
            for (int q = 0; q < 8; ++q) r += red[q];
            rtot = fmaxf(r, 1e-12f);
        }
        __syncthreads();
        const float inv = __frcp_rn(rtot);
        cls[k * CC + tid] = v0 * inv;
        cls[k * CC + 256 + tid] = v1 * inv;
        __syncthreads();
    }

    const int px = tid & 15;
    const int cg = tid >> 4;
    float a0 = 0.f, a1 = 0.f, a2 = 0.f, a3 = 0.f, a4 = 0.f;
    const float* xb = x + ((size_t)b * CC + cg * 32) * HWP + px0 + px;
    #pragma unroll 4
    for (int ci = 0; ci < 32; ++ci) {
        const int c = cg * 32 + ci;
        const float xv = xb[(size_t)ci * HWP];
        a0 += xv * cls[0 * CC + c];
        a1 += xv * cls[1 * CC + c];
        a2 += xv * cls[2 * CC + c];
        a3 += xv * cls[3 * CC + c];
        a4 += xv * cls[4 * CC + c];
    }
    part[cg][px * KK + 0] = a0;
    part[cg][px * KK + 1] = a1;
    part[cg][px * KK + 2] = a2;
    part[cg][px * KK + 3] = a3;
    part[cg][px * KK + 4] = a4;
    __syncthreads();

    if (tid < 16 * KK) {
        float s = 0.f;
        #pragma unroll
        for (int g = 0; g < 16; ++g) s += part[g][tid];
        const int p = tid / KK, k = tid % KK;
        g_bg[((size_t)b * KK + k) * HWP + px0 + p] = __logf(s * 0.3f + 1e-10f);
    }
}

// ---------------------------------------------------------------------------
// fg: block 128 = 4bg(warps) x 4mg x 8pc ; thread tile 8b x 8m x 2px (1 pair).
// EXACT validated R10 mainloop; C split across grid.z (NSPLIT half-blocks) to
// cut the wave-quantization tail; epilogue = raw partial dump to global.
// ---------------------------------------------------------------------------
__global__ void __launch_bounds__(128, 2) fg_kernel(const float* __restrict__ x,
                                                    const float* __restrict__ mix) {
    extern __shared__ float2 arena[];

    const int tid   = threadIdx.x;
    const int mtile = blockIdx.x;        // 7
    const int ptile = blockIdx.y;        // 49
    const int split = blockIdx.z;        // 2
    const int mbase = mtile * MT;
    const int px0   = ptile * PT;

    // ---- loader mapping: c_l = tid>>5 (channels c_l and c_l+4), r = tid&31
    const int c_l = tid >> 5;
    const int r   = tid & 31;
    const int mrow = (mbase + r < MM) ? mbase + r : MM - 1;
    const size_t csoff = (size_t)split * CSPLIT * HWP;
    const float* xsrc = x   + ((size_t)r    * CC + c_l) * HWP + csoff + px0;
    const float* msrc = mix + ((size_t)mrow * CC + c_l) * HWP + csoff + px0;
    const int rowb_f2 = c_l * CHF2 + 72 * (r >> 3) + 8 * (r & 7);
    const int rsw = r & 3;
    const unsigned sm_b = su32(arena);

    // ---- compute mapping (identical to R10)
    const int pc = tid & 7;
    const int mg = (tid >> 3) & 3;
    const int bg = tid >> 5;             // warp id
    int pcx[4];
    #pragma unroll
    for (int t = 0; t < 4; ++t) pcx[t] = 2 * ((pc >> 1) ^ t) + (pc & 1);
    const int xob = bg * 72;
    const int mob = mg * 72;
    const int dof = mob + 8 * bg + pcx[bg];   // dden rows j=bg and j=bg+4

    ull acc[8][8];
    ull dden[2] = {0ull, 0ull};
    #pragma unroll
    for (int i = 0; i < 8; ++i)
        #pragma unroll
        for (int j = 0; j < 8; ++j) acc[i][j] = 0ull;

#define LOAD_STAGE(buf, s)                                                        \
    {                                                                             \
        const size_t go = (size_t)(s) * CT * HWP;                                 \
        _Pragma("unroll")                                                         \
        for (int ch = 0; ch < 2; ++ch) {                                          \
            _Pragma("unroll")                                                     \
            for (int q = 0; q < 4; ++q) {                                         \
                const int df2 = rowb_f2 + ch * (4 * CHF2) + 2 * (q ^ rsw);        \
                unsigned dx = sm_b + (unsigned)(((buf) * BUFF2 + df2) * 8);       \
                unsigned dm = dx + (unsigned)(STAGEF2 * 8);                       \
                asm volatile("cp.async.cg.shared.global [%0], [%1], 16;"          \
                             ::"r"(dx), "l"(xsrc + go + ch * 4 * HWP + 4 * q));   \
                asm volatile("cp.async.cg.shared.global [%0], [%1], 16;"          \
                             ::"r"(dm), "l"(msrc + go + ch * 4 * HWP + 4 * q));   \
            }                                                                     \
        }                                                                         \
        asm volatile("cp.async.commit_group;");                                   \
    }

#define STEP(cur, nxt, s)                                                         \
    {                                                                             \
        asm volatile("cp.async.wait_group 0;");                                   \
        __syncthreads();                                                          \
        {                                                                         \
            const int ns = ((s) + 1 < NSTEP) ? (s) + 1 : NSTEP - 1;               \
            LOAD_STAGE(nxt, ns);                                                  \
        }                                                                         \
        {                                                                         \
            const ull* xb = (const ull*)(arena + (cur) * BUFF2);                  \
            const ull* mb = xb + STAGEF2;                                         \
            _Pragma("unroll")                                                     \
            for (int c = 0; c < CT; ++c) {                                        \
                ull xr[8];                                                        \
                _Pragma("unroll")                                                 \
                for (int i = 0; i < 8; ++i)                                       \
                    xr[i] = xb[c * CHF2 + xob + 8 * i + pcx[i & 3]];              \
                const ull d0 = mb[c * CHF2 + dof];                                \
                const ull d1 = mb[c * CHF2 + dof + 32];                           \
                asm("add.rn.f32x2 %0, %0, %1;" : "+l"(dden[0]) : "l"(d0));        \
                asm("add.rn.f32x2 %0, %0, %1;" : "+l"(dden[1]) : "l"(d1));        \
                _Pragma("unroll")                                                 \
                for (int j = 0; j < 8; ++j) {                                     \
                    const ull mr = mb[c * CHF2 + mob + 8 * j + pcx[j & 3]];       \
                    _Pragma("unroll")                                             \
                    for (int i = 0; i < 8; ++i)                                   \
                        asm("fma.rn.f32x2 %0, %1, %2, %0;"                        \
                            : "+l"(acc[i][j]) : "l"(xr[i]), "l"(mr));             \
                }                                                                 \
            }                                                                     \
        }                                                                         \
    }

    // ---- prologue: stage 0 -> buffer 0
    LOAD_STAGE(0, 0)

    // ---- main loop: 32 steps, unrolled x2 for static buffer indices
    for (int it = 0; it < NSTEP / 2; ++it) {
        const int s = it * 2;
        STEP(0, 1, s)
        STEP(1, 0, s + 1)
    }

    // ---- epilogue: dump partials (no smem reuse, no barriers needed)
    const size_t tix = (size_t)split * NTILE + mtile * 49 + ptile;
    float2* pout = g_part + tix * 8192;
    #pragma unroll
    for (int j = 0; j < 8; ++j)
        #pragma unroll
        for (int i = 0; i < 8; ++i)
            pout[((bg * 8 + i) * 32 + (mg * 8 + j)) * 8 + pc] =
                *(const float2*)&acc[i][j];
    float2* dout = g_pden + tix * 256;
    dout[(mg * 8 + bg) * 8 + pc] = *(const float2*)&dden[0];
    dout[(mg * 8 + bg + 4) * 8 + pc] = *(const float2*)&dden[1];
#undef STEP
#undef LOAD_STAGE
}

// ---------------------------------------------------------------------------
// combine: sum the NSPLIT partials, then log + occlusion-max + g_pm atomics
// (exact R10 fg-epilogue semantics). grid (7,49), block 256.
// ---------------------------------------------------------------------------
__global__ void __launch_bounds__(256) combine_kernel() {
    __shared__ float2 sden[256];

    const int tid   = threadIdx.x;
    const int mtile = blockIdx.x;
    const int ptile = blockIdx.y;
    const int mbase = mtile * MT;
    const int px0   = ptile * PT;

    const size_t t0 = (size_t)mtile * 49 + ptile;
    const size_t t1 = t0 + NTILE;
    const float2* p0 = g_part + t0 * 8192;
    const float2* p1 = g_part + t1 * 8192;

    {
        const float2 a = g_pden[t0 * 256 + tid];
        const float2 b2 = g_pden[t1 * 256 + tid];
        sden[tid] = make_float2(a.x + b2.x, a.y + b2.y);
    }
    __syncthreads();

    #pragma unroll
    for (int rep = 0; rep < 4; ++rep) {
        const int cell = tid + rep * 256;      // 0..1023 = b*32 + ml
        const int b = cell >> 5;
        const int ml = cell & 31;
        const int m_g = mbase + ml;
        float2 fv[8];
        #pragma unroll
        for (int p = 0; p < 8; ++p) {
            const float2 u = p0[cell * 8 + p];
            const float2 v = p1[cell * 8 + p];
            const float2 d = sden[ml * 8 + p];
            const float ivx = __fdividef(0.7f, fmaxf(d.x, 1e-12f));
            const float ivy = __fdividef(0.7f, fmaxf(d.y, 1e-12f));
            fv[p].x = __logf((u.x + v.x) * ivx + 1e-10f);
            fv[p].y = __logf((u.y + v.y) * ivy + 1e-10f);
        }
        float sk[KK];
        #pragma unroll
        for (int k = 0; k < KK; ++k) {
            float s = 0.f;
            const float* bgp = g_bg + ((size_t)b * KK + k) * HWP + px0;
            #pragma unroll
            for (int pp = 0; pp < 4; ++pp) {
                const float4 bv = *(const float4*)(bgp + pp * 4);
                s += fmaxf(fv[2 * pp].x, bv.x) + fmaxf(fv[2 * pp].y, bv.y) +
                     fmaxf(fv[2 * pp + 1].x, bv.z) + fmaxf(fv[2 * pp + 1].y, bv.w);
            }
            sk[k] = s;
        }
        if (m_g < MM) {
            float* pmp = g_pm + ((size_t)b * MM + m_g) * KK;
            #pragma unroll
            for (int k = 0; k < KK; ++k) atomicAdd(&pmp[k], sk[k]);
        }
    }
}

// ---------------------------------------------------------------------------
__global__ void final_kernel(float* __restrict__ out) {
    const int idx = blockIdx.x * 256 + threadIdx.x;
    if (idx >= BB * NCC) return;
    const int b = idx / NCC, nc = idx % NCC;
    const float* p = g_pm + ((size_t)b * MM + nc * NMM) * KK;
    float m = -3.402823466e+38f;
    #pragma unroll
    for (int t = 0; t < NMM * KK; ++t) m = fmaxf(m, p[t]);
    out[idx] = m;
}

// ---------------------------------------------------------------------------
extern "C" void kernel_launch(void* const* d_in, const int* in_sizes, int n_in,
                              void* d_out, int out_size) {
    const float* x       = (const float*)d_in[0];
    const float* mix     = (const float*)d_in[1];
    const float* clutter = (const float*)d_in[2];
    float* out = (float*)d_out;

    const int fg_smem = ARENAF2 * 8;     // 73728 B, 2 CTAs/SM
    cudaFuncSetAttribute(fg_kernel, cudaFuncAttributeMaxDynamicSharedMemorySize,
                         fg_smem);

    bg_kernel<<<dim3(49, BB), 256>>>(x, clutter);
    fg_kernel<<<dim3(7, 49, NSPLIT), 128, fg_smem>>>(x, mix);
    combine_kernel<<<dim3(7, 49), 256>>>();
    final_kernel<<<(BB * NCC + 255) / 256, 256>>>(out);
}

// round 14
// speedup vs baseline: 1.3625x; 1.0904x over previous
#include <cuda_runtime.h>
#include <cstdint>

#define BB 32
#define CC 512
#define HWP 784
#define MM 200
#define NCC 50
#define NMM 4
#define KK 5

#define MT 32
#define PT 16            // pixels per tile (8 pairs)
#define CT 8             // channels per pipeline step
#define SPT 64           // steps per tile (CC / CT)
#define NTILE (7 * 49)   // 343 (m,p) tiles
#define TOTW (NTILE * SPT)          // 21952 step-units
#define NCTA 304                    // 152 SMs x 2 resident CTAs
#define BASEW (TOTW / NCTA)         // 72
#define REMW (TOTW - BASEW * NCTA) // 64 CTAs get one extra step

// smem layout (float2 units), per-channel layout identical to validated R10:
// per channel per operand: 4 groups of 8 rows, group stride 72 f2
// (8 rows x 8 f2 + 8 f2 pad); within each row the four 16B chunks are
// XOR-swizzled by (row&3). Two pipeline buffers (double buffer).
#define CHF2 288                   // 4 * 72
#define STAGEF2 (CT * CHF2)        // 2304 per operand
#define BUFF2 (2 * STAGEF2)        // x + m = 4608
#define ARENAF2 (2 * BUFF2)        // 9216 f2 = 73728 B

typedef unsigned long long ull;

__device__ float g_bg[BB * KK * HWP];
__device__ float g_pm[BB * MM * KK];
// per-tile accumulators (red.add targets): [tile][b(32)][m(32)][pc(8)] float2
__device__ float2 g_acc[NTILE * 8192];          // 22.5 MB
// per-tile denominators: [tile][m(32)][pc(8)] float2
__device__ float2 g_aden[NTILE * 256];          // 0.7 MB

__device__ __forceinline__ unsigned su32(const void* p) {
    return (unsigned)__cvta_generic_to_shared(p);
}

__device__ __forceinline__ void red2(float2* p, ull v) {
    const float2 f = *(const float2*)&v;
    asm volatile("red.global.add.v2.f32 [%0], {%1, %2};"
                 :: "l"(p), "f"(f.x), "f"(f.y) : "memory");
}

// ---------------------------------------------------------------------------
// bg (+ fused clutter normalization + zeroing of g_pm / g_acc / g_aden)
// ---------------------------------------------------------------------------
__global__ void __launch_bounds__(256) bg_kernel(const float* __restrict__ x,
                                                 const float* __restrict__ clutter) {
    __shared__ float cls[KK * CC];
    __shared__ float part[16][16 * KK];
    __shared__ float red[8];
    __shared__ float rtot;

    const int tid = threadIdx.x;
    const int b = blockIdx.y;
    const int px0 = blockIdx.x * 16;
    const int lane = tid & 31, w = tid >> 5;

    // zero scratch (401408 threads total)
    const int gid = (blockIdx.y * 49 + blockIdx.x) * 256 + tid;
    if (gid < BB * MM * KK) g_pm[gid] = 0.0f;
    const float2 z2 = make_float2(0.f, 0.f);
    for (int i = gid; i < NTILE * 8192; i += 49 * BB * 256) g_acc[i] = z2;
    if (gid < NTILE * 256) g_aden[gid] = z2;

    for (int k = 0; k < KK; ++k) {
        float v0 = fminf(fmaxf(clutter[k * CC + tid], 0.f), 1.f);
        float v1 = fminf(fmaxf(clutter[k * CC + 256 + tid], 0.f), 1.f);
        float s = v0 + v1;
        #pragma unroll
        for (int o = 16; o > 0; o >>= 1) s += __shfl_xor_sync(0xffffffffu, s, o);
        if (lane == 0) red[w] = s;
        __syncthreads();
        if (tid == 0) {
            float r = 0.f;
            #pragma unroll
            for (int q = 0; q < 8; ++q) r += red[q];
            rtot = fmaxf(r, 1e-12f);
        }
        __syncthreads();
        const float inv = __frcp_rn(rtot);
        cls[k * CC + tid] = v0 * inv;
        cls[k * CC + 256 + tid] = v1 * inv;
        __syncthreads();
    }

    const int px = tid & 15;
    const int cg = tid >> 4;
    float a0 = 0.f, a1 = 0.f, a2 = 0.f, a3 = 0.f, a4 = 0.f;
    const float* xb = x + ((size_t)b * CC + cg * 32) * HWP + px0 + px;
    #pragma unroll 4
    for (int ci = 0; ci < 32; ++ci) {
        const int c = cg * 32 + ci;
        const float xv = xb[(size_t)ci * HWP];
        a0 += xv * cls[0 * CC + c];
        a1 += xv * cls[1 * CC + c];
        a2 += xv * cls[2 * CC + c];
        a3 += xv * cls[3 * CC + c];
        a4 += xv * cls[4 * CC + c];
    }
    part[cg][px * KK + 0] = a0;
    part[cg][px * KK + 1] = a1;
    part[cg][px * KK + 2] = a2;
    part[cg][px * KK + 3] = a3;
    part[cg][px * KK + 4] = a4;
    __syncthreads();

    if (tid < 16 * KK) {
        float s = 0.f;
        #pragma unroll
        for (int g = 0; g < 16; ++g) s += part[g][tid];
        const int p = tid / KK, k = tid % KK;
        g_bg[((size_t)b * KK + k) * HWP + px0 + p] = __logf(s * 0.3f + 1e-10f);
    }
}

// ---------------------------------------------------------------------------
// fg: 304 persistent-style CTAs, each owns a contiguous 72-73 step range of
// the flattened (tile, step) work list -> perfectly balanced, <=3 fragments.
// Mainloop per fragment identical to the validated R10/R13 core.
// Partials land in g_acc / g_aden via red.global.add.v2.f32.
// ---------------------------------------------------------------------------
__global__ void __launch_bounds__(128, 2) fg_kernel(const float* __restrict__ x,
                                                    const float* __restrict__ mix) {
    extern __shared__ float2 arena[];

    const int tid = threadIdx.x;
    const int cta = blockIdx.x;
    int pos = cta * BASEW + (cta < REMW ? cta : REMW);
    const int end = pos + BASEW + (cta < REMW ? 1 : 0);

    // ---- tile-independent mappings
    const int c_l = tid >> 5;
    const int r   = tid & 31;
    const int rowb_f2 = c_l * CHF2 + 72 * (r >> 3) + 8 * (r & 7);
    const int rsw = r & 3;
    const unsigned sm_b = su32(arena);

    const int pc = tid & 7;
    const int mg = (tid >> 3) & 3;
    const int bg = tid >> 5;
    int pcx[4];
    #pragma unroll
    for (int t = 0; t < 4; ++t) pcx[t] = 2 * ((pc >> 1) ^ t) + (pc & 1);
    const int xob = bg * 72;
    const int mob = mg * 72;
    const int dof = mob + 8 * bg + pcx[bg & 3];

#define LOAD_STAGE(buf, s)                                                        \
    {                                                                             \
        const size_t go = (size_t)(s) * CT * HWP;                                 \
        _Pragma("unroll")                                                         \
        for (int ch = 0; ch < 2; ++ch) {                                          \
            _Pragma("unroll")                                                     \
            for (int q = 0; q < 4; ++q) {                                         \
                const int df2 = rowb_f2 + ch * (4 * CHF2) + 2 * (q ^ rsw);        \
                unsigned dx = sm_b + (unsigned)(((buf) * BUFF2 + df2) * 8);       \
                unsigned dm = dx + (unsigned)(STAGEF2 * 8);                       \
                asm volatile("cp.async.cg.shared.global [%0], [%1], 16;"          \
                             ::"r"(dx), "l"(xsrc + go + ch * 4 * HWP + 4 * q));   \
                asm volatile("cp.async.cg.shared.global [%0], [%1], 16;"          \
                             ::"r"(dm), "l"(msrc + go + ch * 4 * HWP + 4 * q));   \
            }                                                                     \
        }                                                                         \
        asm volatile("cp.async.commit_group;");                                   \
    }

    while (pos < end) {
        const int tile = pos >> 6;               // /SPT (64)
        const int s0   = pos & (SPT - 1);
        const int rem  = end - pos;
        const int avail = SPT - s0;
        const int nst  = (rem < avail) ? rem : avail;

        const int mtile = tile / 49;
        const int ptile = tile - mtile * 49;
        const int mbase = mtile * MT;
        const int px0   = ptile * PT;
        const int mrow  = (mbase + r < MM) ? mbase + r : MM - 1;
        const float* xsrc = x   + ((size_t)r    * CC + c_l) * HWP + px0;
        const float* msrc = mix + ((size_t)mrow * CC + c_l) * HWP + px0;

        ull acc[8][8];
        ull dden[2] = {0ull, 0ull};
        #pragma unroll
        for (int i = 0; i < 8; ++i)
            #pragma unroll
            for (int j = 0; j < 8; ++j) acc[i][j] = 0ull;

        // prologue: step s0 -> buffer 0
        LOAD_STAGE(0, s0)

        for (int t = 0; t < nst; ++t) {
            const int cur = t & 1;
            const int nxt = cur ^ 1;
            const int lds = s0 + ((t + 1 < nst) ? t + 1 : t);

            asm volatile("cp.async.wait_group 0;");
            __syncthreads();
            LOAD_STAGE(nxt, lds)

            const ull* xb = (const ull*)(arena + cur * BUFF2);
            const ull* mb = xb + STAGEF2;
            #pragma unroll
            for (int c = 0; c < CT; ++c) {
                ull xr[8];
                #pragma unroll
                for (int i = 0; i < 8; ++i)
                    xr[i] = xb[c * CHF2 + xob + 8 * i + pcx[i & 3]];
                const ull d0 = mb[c * CHF2 + dof];
                const ull d1 = mb[c * CHF2 + dof + 32];
                asm("add.rn.f32x2 %0, %0, %1;" : "+l"(dden[0]) : "l"(d0));
                asm("add.rn.f32x2 %0, %0, %1;" : "+l"(dden[1]) : "l"(d1));
                #pragma unroll
                for (int j = 0; j < 8; ++j) {
                    const ull mr = mb[c * CHF2 + mob + 8 * j + pcx[j & 3]];
                    #pragma unroll
                    for (int i = 0; i < 8; ++i)
                        asm("fma.rn.f32x2 %0, %1, %2, %0;"
                            : "+l"(acc[i][j]) : "l"(xr[i]), "l"(mr));
                }
            }
        }

        // fragment epilogue: atomic partial dump (disjoint-in-time, <=2 per addr)
        float2* aout = g_acc + (size_t)tile * 8192;
        #pragma unroll
        for (int j = 0; j < 8; ++j)
            #pragma unroll
            for (int i = 0; i < 8; ++i)
                red2(&aout[((bg * 8 + i) * 32 + (mg * 8 + j)) * 8 + pc],
                     acc[i][j]);
        red2(&g_aden[tile * 256 + (mg * 8 + bg) * 8 + pc], dden[0]);
        red2(&g_aden[tile * 256 + (mg * 8 + bg + 4) * 8 + pc], dden[1]);

        pos += nst;
    }
#undef LOAD_STAGE
}

// ---------------------------------------------------------------------------
// combine: normalize + log + occlusion-max + g_pm atomics. grid 343, block 256.
// ---------------------------------------------------------------------------
__global__ void __launch_bounds__(256) combine_kernel() {
    __shared__ float2 sden[256];

    const int tid   = threadIdx.x;
    const int tile  = blockIdx.x;
    const int mtile = tile / 49;
    const int ptile = tile - mtile * 49;
    const int mbase = mtile * MT;
    const int px0   = ptile * PT;

    const float2* pa = g_acc + (size_t)tile * 8192;
    sden[tid] = g_aden[tile * 256 + tid];
    __syncthreads();

    #pragma unroll
    for (int rep = 0; rep < 4; ++rep) {
        const int cell = tid + rep * 256;      // 0..1023 = b*32 + ml
        const int b = cell >> 5;
        const int ml = cell & 31;
        const int m_g = mbase + ml;
        float2 fv[8];
        #pragma unroll
        for (int p = 0; p < 8; ++p) {
            const float2 u = pa[cell * 8 + p];
            const float2 d = sden[ml * 8 + p];
            const float ivx = __fdividef(0.7f, fmaxf(d.x, 1e-12f));
            const float ivy = __fdividef(0.7f, fmaxf(d.y, 1e-12f));
            fv[p].x = __logf(u.x * ivx + 1e-10f);
            fv[p].y = __logf(u.y * ivy + 1e-10f);
        }
        float sk[KK];
        #pragma unroll
        for (int k = 0; k < KK; ++k) {
            float s = 0.f;
            const float* bgp = g_bg + ((size_t)b * KK + k) * HWP + px0;
            #pragma unroll
            for (int pp = 0; pp < 4; ++pp) {
                const float4 bv = *(const float4*)(bgp + pp * 4);
                s += fmaxf(fv[2 * pp].x, bv.x) + fmaxf(fv[2 * pp].y, bv.y) +
                     fmaxf(fv[2 * pp + 1].x, bv.z) + fmaxf(fv[2 * pp + 1].y, bv.w);
            }
            sk[k] = s;
        }
        if (m_g < MM) {
            float* pmp = g_pm + ((size_t)b * MM + m_g) * KK;
            #pragma unroll
            for (int k = 0; k < KK; ++k) atomicAdd(&pmp[k], sk[k]);
        }
    }
}

// ---------------------------------------------------------------------------
__global__ void final_kernel(float* __restrict__ out) {
    const int idx = blockIdx.x * 256 + threadIdx.x;
    if (idx >= BB * NCC) return;
    const int b = idx / NCC, nc = idx % NCC;
    const float* p = g_pm + ((size_t)b * MM + nc * NMM) * KK;
    float m = -3.402823466e+38f;
    #pragma unroll
    for (int t = 0; t < NMM * KK; ++t) m = fmaxf(m, p[t]);
    out[idx] = m;
}

// ---------------------------------------------------------------------------
extern "C" void kernel_launch(void* const* d_in, const int* in_sizes, int n_in,
                              void* d_out, int out_size) {
    const float* x       = (const float*)d_in[0];
    const float* mix     = (const float*)d_in[1];
    const float* clutter = (const float*)d_in[2];
    float* out = (float*)d_out;

    const int fg_smem = ARENAF2 * 8;     // 73728 B, 2 CTAs/SM
    cudaFuncSetAttribute(fg_kernel, cudaFuncAttributeMaxDynamicSharedMemorySize,
                         fg_smem);

    bg_kernel<<<dim3(49, BB), 256>>>(x, clutter);
    fg_kernel<<<NCTA, 128, fg_smem>>>(x, mix);
    combine_kernel<<<NTILE, 256>>>();
    final_kernel<<<(BB * NCC + 255) / 256, 256>>>(out);
}